// round 3
// baseline (speedup 1.0000x reference)
#include <cuda_runtime.h>

// Problem constants
#define DIMC  128
#define NTQ   4096       // target tokens (64x64)
#define NSK   1024       // source tokens (32x32)
#define BATCH 8
#define OUT_FLOATS_FULL 8388608LL   // 8*128*4096*2 (interleaved complex floats)

// ---------------------------------------------------------------------------
// Scratch (static __device__ globals; no allocation allowed)
// ---------------------------------------------------------------------------
__device__ float g_Wc[3][256 * 256];                       // combined complex weights (k-major)
__device__ float g_bc[3][256];                             // combined bias [re|im]
__device__ float g_Q[(size_t)BATCH * NTQ * 256];           // [b][n][re0..127|im0..127]
__device__ float g_K[(size_t)BATCH * NSK * 256];
__device__ float g_V[(size_t)BATCH * NSK * 256];
__device__ float g_S[(size_t)BATCH * NTQ * NSK];           // attention scores / probs

// ---------------------------------------------------------------------------
// Prep: combined weights + biases so every complex op becomes one real GEMM.
// A[n][k] = [tr|ti] (k in 0..255):
//   Wc[k][d]      = Wr[d][k]       (k<128)
//   Wc[k][d]      = -Wi[d][k-128]  (k>=128)
//   Wc[k][128+d]  = Wi[d][k]       (k<128)
//   Wc[k][128+d]  = Wr[d][k-128]   (k>=128)
// ---------------------------------------------------------------------------
__global__ void prep_kernel(const float* __restrict__ Wq_r, const float* __restrict__ Wq_i,
                            const float* __restrict__ Wk_r, const float* __restrict__ Wk_i,
                            const float* __restrict__ Wv_r, const float* __restrict__ Wv_i,
                            const float* __restrict__ bq_r, const float* __restrict__ bq_i,
                            const float* __restrict__ bk_r, const float* __restrict__ bk_i,
                            const float* __restrict__ bv_r, const float* __restrict__ bv_i)
{
    int idx = blockIdx.x * blockDim.x + threadIdx.x;
    if (idx < 3 * 128 * 128) {
        int mat = idx / 16384;
        int r   = idx % 16384;
        int d   = r / 128;
        int c   = r % 128;
        const float* Wr = (mat == 0) ? Wq_r : (mat == 1) ? Wk_r : Wv_r;
        const float* Wi = (mat == 0) ? Wq_i : (mat == 1) ? Wk_i : Wv_i;
        float wr = Wr[d * 128 + c];
        float wi = Wi[d * 128 + c];
        float* Wc = g_Wc[mat];
        Wc[c * 256 + d]               = wr;
        Wc[(c + 128) * 256 + d]       = -wi;
        Wc[c * 256 + 128 + d]         = wi;
        Wc[(c + 128) * 256 + 128 + d] = wr;
    }
    if (idx < 3 * 128) {
        int mat = idx / 128;
        int d   = idx % 128;
        const float* br = (mat == 0) ? bq_r : (mat == 1) ? bk_r : bv_r;
        const float* bi = (mat == 0) ? bq_i : (mat == 1) ? bk_i : bv_i;
        g_bc[mat][d]       = br[d];
        g_bc[mat][128 + d] = bi[d];
    }
}

// ---------------------------------------------------------------------------
// Double-buffered SGEMM: 128x128 tile, BK=16, 256 threads, 8x8 micro-tile.
// One __syncthreads per k-tile; gmem prefetch into registers overlaps compute.
// MODE 0 (PROJ): A gathered from [re|im] planes (elem (m,k) at plane[k]*M+m),
//                B = g_Wc[sel], C = g_{Q,K,V} (+bias). sel<0 packs K&V in one
//                launch: gridDim.x=4, sel = 1+(bx>>1), n0 = (bx&1)*128.
// MODE 1 (QK)  : A = g_Q [M][256], B = g_K as B^T ([N][K]), C = g_S * alpha.
// MODE 2 (AV)  : A = g_S [M][1024], B = g_V [K][256], C = d_out transposed +
//                gamma-scaled interleaved complex; every store bounds-guarded.
// ---------------------------------------------------------------------------
template<int MODE, int N, int K>
__global__ __launch_bounds__(256, 2)
void gemm_kernel(const float* __restrict__ A0, const float* __restrict__ A1,
                 int sel_param, float* __restrict__ Out,
                 const float* __restrict__ gammap, int M, long long out_elems)
{
    const int b   = blockIdx.z;
    const int m0  = blockIdx.y * 128;
    int sel = sel_param;
    int n0  = blockIdx.x * 128;
    if (MODE == 0 && sel_param < 0) {          // packed K|V projection launch
        sel = 1 + (blockIdx.x >> 1);
        n0  = (blockIdx.x & 1) * 128;
    }
    const int tid = threadIdx.x;
    const int tx  = tid & 15;
    const int ty  = tid >> 4;

    __shared__ float As[2][16][128];
    __shared__ float Bs[2][16][128];

    const float* Ar = nullptr;
    const float* Ai = nullptr;
    const float* Bp = nullptr;
    if (MODE == 0) {
        Ar = A0 + (size_t)b * DIMC * M;   // real plane, [c][m]
        Ai = A1 + (size_t)b * DIMC * M;   // imag plane
        Bp = g_Wc[sel];
    } else if (MODE == 1) {
        Ar = g_Q + (size_t)b * M * K;     // row-major, lda = K
        Bp = g_K + (size_t)b * N * K;     // [N][K] (transposed operand)
    } else {
        Ar = g_S + (size_t)b * M * K;     // row-major, lda = K
        Bp = g_V + (size_t)b * K * N;     // [K][N]
    }

    // per-thread load coordinates
    const int a_kl = tid >> 4;            // MODE 0: k within tile (0..15)
    const int a_ml8 = (tid & 15) << 3;    // MODE 0: m within tile (0,8,...,120)
    const int a_ml = tid >> 1;            // MODE 1/2: m within tile (0..127)
    const int a_kq = (tid & 1) << 3;      // MODE 1/2: k within tile (0 or 8)
    const int b_kl = tid >> 4;            // MODE 0/2
    const int b_nl8 = (tid & 15) << 3;    // MODE 0/2
    const int b_nl = tid >> 1;            // MODE 1
    const int b_kq = (tid & 1) << 3;      // MODE 1

    float acc[8][8];
#pragma unroll
    for (int i = 0; i < 8; i++)
#pragma unroll
        for (int j = 0; j < 8; j++) acc[i][j] = 0.0f;

    // ---- initial tile -> smem buffer 0 ----
    {
        if (MODE == 0) {
            int kg = a_kl;
            const float* src = ((kg < DIMC) ? (Ar + (size_t)kg * M)
                                            : (Ai + (size_t)(kg - DIMC) * M)) + m0 + a_ml8;
            *(float4*)&As[0][a_kl][a_ml8]     = ((const float4*)src)[0];
            *(float4*)&As[0][a_kl][a_ml8 + 4] = ((const float4*)src)[1];
        } else {
            const float* p = Ar + (size_t)(m0 + a_ml) * K + a_kq;
            float4 v0 = ((const float4*)p)[0];
            float4 v1 = ((const float4*)p)[1];
            As[0][a_kq + 0][a_ml] = v0.x; As[0][a_kq + 1][a_ml] = v0.y;
            As[0][a_kq + 2][a_ml] = v0.z; As[0][a_kq + 3][a_ml] = v0.w;
            As[0][a_kq + 4][a_ml] = v1.x; As[0][a_kq + 5][a_ml] = v1.y;
            As[0][a_kq + 6][a_ml] = v1.z; As[0][a_kq + 7][a_ml] = v1.w;
        }
        if (MODE == 1) {
            const float* p = Bp + (size_t)(n0 + b_nl) * K + b_kq;
            float4 v0 = ((const float4*)p)[0];
            float4 v1 = ((const float4*)p)[1];
            Bs[0][b_kq + 0][b_nl] = v0.x; Bs[0][b_kq + 1][b_nl] = v0.y;
            Bs[0][b_kq + 2][b_nl] = v0.z; Bs[0][b_kq + 3][b_nl] = v0.w;
            Bs[0][b_kq + 4][b_nl] = v1.x; Bs[0][b_kq + 5][b_nl] = v1.y;
            Bs[0][b_kq + 6][b_nl] = v1.z; Bs[0][b_kq + 7][b_nl] = v1.w;
        } else {
            const float* p = Bp + (size_t)b_kl * N + n0 + b_nl8;
            *(float4*)&Bs[0][b_kl][b_nl8]     = ((const float4*)p)[0];
            *(float4*)&Bs[0][b_kl][b_nl8 + 4] = ((const float4*)p)[1];
        }
    }
    __syncthreads();

    int buf = 0;
#pragma unroll 1
    for (int k0 = 0; k0 < K; k0 += 16) {
        const bool has_next = (k0 + 16 < K);
        float4 ra0, ra1, rb0, rb1;

        // ---- prefetch next tile gmem -> regs ----
        if (has_next) {
            const int kn = k0 + 16;
            if (MODE == 0) {
                int kg = kn + a_kl;
                const float* src = ((kg < DIMC) ? (Ar + (size_t)kg * M)
                                                : (Ai + (size_t)(kg - DIMC) * M)) + m0 + a_ml8;
                ra0 = ((const float4*)src)[0];
                ra1 = ((const float4*)src)[1];
            } else {
                const float* p = Ar + (size_t)(m0 + a_ml) * K + kn + a_kq;
                ra0 = ((const float4*)p)[0];
                ra1 = ((const float4*)p)[1];
            }
            if (MODE == 1) {
                const float* p = Bp + (size_t)(n0 + b_nl) * K + kn + b_kq;
                rb0 = ((const float4*)p)[0];
                rb1 = ((const float4*)p)[1];
            } else {
                const float* p = Bp + (size_t)(kn + b_kl) * N + n0 + b_nl8;
                rb0 = ((const float4*)p)[0];
                rb1 = ((const float4*)p)[1];
            }
        }

        // ---- compute on current buffer ----
#pragma unroll
        for (int kk = 0; kk < 16; kk++) {
            float a[8], bb[8];
            *(float4*)&a[0]  = *(const float4*)&As[buf][kk][ty * 8];
            *(float4*)&a[4]  = *(const float4*)&As[buf][kk][ty * 8 + 4];
            *(float4*)&bb[0] = *(const float4*)&Bs[buf][kk][tx * 8];
            *(float4*)&bb[4] = *(const float4*)&Bs[buf][kk][tx * 8 + 4];
#pragma unroll
            for (int i = 0; i < 8; i++)
#pragma unroll
                for (int j = 0; j < 8; j++)
                    acc[i][j] = fmaf(a[i], bb[j], acc[i][j]);
        }

        // ---- stage prefetched regs -> other buffer ----
        if (has_next) {
            int nb = buf ^ 1;
            if (MODE == 0) {
                *(float4*)&As[nb][a_kl][a_ml8]     = ra0;
                *(float4*)&As[nb][a_kl][a_ml8 + 4] = ra1;
            } else {
                As[nb][a_kq + 0][a_ml] = ra0.x; As[nb][a_kq + 1][a_ml] = ra0.y;
                As[nb][a_kq + 2][a_ml] = ra0.z; As[nb][a_kq + 3][a_ml] = ra0.w;
                As[nb][a_kq + 4][a_ml] = ra1.x; As[nb][a_kq + 5][a_ml] = ra1.y;
                As[nb][a_kq + 6][a_ml] = ra1.z; As[nb][a_kq + 7][a_ml] = ra1.w;
            }
            if (MODE == 1) {
                Bs[nb][b_kq + 0][b_nl] = rb0.x; Bs[nb][b_kq + 1][b_nl] = rb0.y;
                Bs[nb][b_kq + 2][b_nl] = rb0.z; Bs[nb][b_kq + 3][b_nl] = rb0.w;
                Bs[nb][b_kq + 4][b_nl] = rb1.x; Bs[nb][b_kq + 5][b_nl] = rb1.y;
                Bs[nb][b_kq + 6][b_nl] = rb1.z; Bs[nb][b_kq + 7][b_nl] = rb1.w;
            } else {
                *(float4*)&Bs[nb][b_kl][b_nl8]     = rb0;
                *(float4*)&Bs[nb][b_kl][b_nl8 + 4] = rb1;
            }
        }
        __syncthreads();
        buf ^= 1;
    }

    // ---- epilogue ----
    if (MODE == 0) {
        float* C = ((sel == 0) ? g_Q : (sel == 1) ? g_K : g_V) + (size_t)b * M * 256;
#pragma unroll
        for (int i = 0; i < 8; i++) {
            int m = m0 + ty * 8 + i;
#pragma unroll
            for (int j = 0; j < 8; j++) {
                int n = n0 + tx * 8 + j;
                C[(size_t)m * 256 + n] = acc[i][j] + g_bc[sel][n];
            }
        }
    } else if (MODE == 1) {
        const float alpha = 0.08838834764831845f;   // 1/sqrt(128)
        float* C = g_S + (size_t)b * M * N;
#pragma unroll
        for (int i = 0; i < 8; i++) {
            int m = m0 + ty * 8 + i;
#pragma unroll
            for (int j = 0; j < 8; j++) {
                int n = n0 + tx * 8 + j;
                C[(size_t)m * N + n] = acc[i][j] * alpha;
            }
        }
    } else {
        float g = (gammap != nullptr) ? *gammap : 0.1f;
        bool full = (out_elems >= OUT_FLOATS_FULL);
#pragma unroll
        for (int i = 0; i < 8; i++) {
            int m = m0 + ty * 8 + i;
#pragma unroll
            for (int j = 0; j < 8; j++) {
                int n  = n0 + tx * 8 + j;
                int d  = n & 127;
                int im = n >> 7;
                if (full) {
                    long long idx = (((long long)b * DIMC + d) * M + m) * 2 + im;
                    if (idx < OUT_FLOATS_FULL) Out[idx] = g * acc[i][j];
                } else if (im == 0) {
                    long long idx = ((long long)b * DIMC + d) * M + m;
                    if (idx < out_elems) Out[idx] = g * acc[i][j];
                }
            }
        }
    }
}

// ---------------------------------------------------------------------------
// Row softmax over g_S: 32768 rows x 1024 cols, one block per row.
// ---------------------------------------------------------------------------
__global__ __launch_bounds__(256)
void softmax_kernel()
{
    size_t row = blockIdx.x;
    float* p = g_S + row * (size_t)NSK;
    int t   = threadIdx.x;
    int wid = t >> 5;
    int ln  = t & 31;

    float4 v = ((const float4*)p)[t];
    float mx = fmaxf(fmaxf(v.x, v.y), fmaxf(v.z, v.w));
#pragma unroll
    for (int o = 16; o; o >>= 1) mx = fmaxf(mx, __shfl_xor_sync(0xffffffffu, mx, o));

    __shared__ float red[8];
    if (ln == 0) red[wid] = mx;
    __syncthreads();
    mx = red[0];
#pragma unroll
    for (int w = 1; w < 8; w++) mx = fmaxf(mx, red[w]);

    v.x = __expf(v.x - mx);
    v.y = __expf(v.y - mx);
    v.z = __expf(v.z - mx);
    v.w = __expf(v.w - mx);
    float s = (v.x + v.y) + (v.z + v.w);
#pragma unroll
    for (int o = 16; o; o >>= 1) s += __shfl_xor_sync(0xffffffffu, s, o);

    __syncthreads();
    if (ln == 0) red[wid] = s;
    __syncthreads();
    s = red[0];
#pragma unroll
    for (int w = 1; w < 8; w++) s += red[w];

    float inv = 1.0f / s;
    v.x *= inv; v.y *= inv; v.z *= inv; v.w *= inv;
    ((float4*)p)[t] = v;
}

// ---------------------------------------------------------------------------
// Launch
// ---------------------------------------------------------------------------
extern "C" void kernel_launch(void* const* d_in, const int* in_sizes, int n_in,
                              void* d_out, int out_size)
{
    const float* target_r = (const float*)d_in[0];
    const float* target_i = (const float*)d_in[1];
    const float* source_r = (const float*)d_in[2];
    const float* source_i = (const float*)d_in[3];
    const float* Wq_r = (const float*)d_in[4];
    const float* Wq_i = (const float*)d_in[5];
    const float* bq_r = (const float*)d_in[6];
    const float* bq_i = (const float*)d_in[7];
    const float* Wk_r = (const float*)d_in[8];
    const float* Wk_i = (const float*)d_in[9];
    const float* bk_r = (const float*)d_in[10];
    const float* bk_i = (const float*)d_in[11];
    const float* Wv_r = (const float*)d_in[12];
    const float* Wv_i = (const float*)d_in[13];
    const float* bv_r = (const float*)d_in[14];
    const float* bv_i = (const float*)d_in[15];
    const float* gamma = (n_in >= 17) ? (const float*)d_in[16] : nullptr;
    float* out = (float*)d_out;
    long long out_elems = (long long)out_size;

    // 1) combined weights/biases
    prep_kernel<<<192, 256>>>(Wq_r, Wq_i, Wk_r, Wk_i, Wv_r, Wv_i,
                              bq_r, bq_i, bk_r, bk_i, bv_r, bv_i);

    // 2) projections: Q (target); K and V packed into one launch (source)
    gemm_kernel<0, 256, 256><<<dim3(2, NTQ / 128, BATCH), 256>>>(
        target_r, target_i, 0, nullptr, nullptr, NTQ, 0);
    gemm_kernel<0, 256, 256><<<dim3(4, NSK / 128, BATCH), 256>>>(
        source_r, source_i, -1, nullptr, nullptr, NSK, 0);

    // 3) scores S = Re(Q K^H) / sqrt(C)
    gemm_kernel<1, NSK, 256><<<dim3(NSK / 128, NTQ / 128, BATCH), 256>>>(
        nullptr, nullptr, 0, nullptr, nullptr, NTQ, 0);

    // 4) softmax rows
    softmax_kernel<<<BATCH * NTQ, 256>>>();

    // 5) out = gamma * (P @ V), transposed + interleaved complex
    gemm_kernel<2, 256, NSK><<<dim3(2, NTQ / 128, BATCH), 256>>>(
        nullptr, nullptr, 0, out, gamma, NTQ, out_elems);
}

// round 11
// speedup vs baseline: 1.2346x; 1.2346x over previous
#include <cuda_runtime.h>
#include <cuda_bf16.h>
#include <cstdint>

// Problem constants
#define DIMC  128
#define NTQ   4096       // target tokens (64x64)
#define NSK   1024       // source tokens (32x32)
#define BATCH 8
#define OUT_FLOATS_FULL 8388608LL   // 8*128*4096*2 interleaved complex floats

// ---------------------------------------------------------------------------
// Scratch (static __device__ globals; no allocation allowed)
// ---------------------------------------------------------------------------
__device__ float g_Wc[3][256 * 256];                        // combined complex weights
__device__ float g_bc[3][256];                              // combined bias [re|im]
__device__ __align__(16) __nv_bfloat16 g_Qh[(size_t)BATCH * NTQ * 256];  // Q hi/lo [b][m][k]
__device__ __align__(16) __nv_bfloat16 g_Ql[(size_t)BATCH * NTQ * 256];
__device__ __align__(16) __nv_bfloat16 g_Kh[(size_t)BATCH * NSK * 256];  // K hi/lo [b][n][k]
__device__ __align__(16) __nv_bfloat16 g_Kl[(size_t)BATCH * NSK * 256];
__device__ float g_V[(size_t)BATCH * NSK * 256];            // V fp32 [b][token][dim]
__device__ float g_S[(size_t)BATCH * NTQ * NSK];            // scores / probs (fp32)

// ---------------------------------------------------------------------------
// Helpers
// ---------------------------------------------------------------------------
__device__ __forceinline__ void mma16816(float* c, const uint32_t* a, const uint32_t* b) {
    asm volatile("mma.sync.aligned.m16n8k16.row.col.f32.bf16.bf16.f32 "
                 "{%0,%1,%2,%3}, {%4,%5,%6,%7}, {%8,%9}, {%0,%1,%2,%3};"
                 : "+f"(c[0]), "+f"(c[1]), "+f"(c[2]), "+f"(c[3])
                 : "r"(a[0]), "r"(a[1]), "r"(a[2]), "r"(a[3]), "r"(b[0]), "r"(b[1]));
}
__device__ __forceinline__ void split_bf16(float x, __nv_bfloat16& h, __nv_bfloat16& l) {
    h = __float2bfloat16(x);
    l = __float2bfloat16(x - __bfloat162float(h));
}

// ---------------------------------------------------------------------------
// Prep: combined weights + biases (round-3 proven).
// ---------------------------------------------------------------------------
__global__ void prep_kernel(const float* __restrict__ Wq_r, const float* __restrict__ Wq_i,
                            const float* __restrict__ Wk_r, const float* __restrict__ Wk_i,
                            const float* __restrict__ Wv_r, const float* __restrict__ Wv_i,
                            const float* __restrict__ bq_r, const float* __restrict__ bq_i,
                            const float* __restrict__ bk_r, const float* __restrict__ bk_i,
                            const float* __restrict__ bv_r, const float* __restrict__ bv_i)
{
    int idx = blockIdx.x * blockDim.x + threadIdx.x;
    if (idx < 3 * 128 * 128) {
        int mat = idx / 16384;
        int r   = idx % 16384;
        int d   = r / 128;
        int c   = r % 128;
        const float* Wr = (mat == 0) ? Wq_r : (mat == 1) ? Wk_r : Wv_r;
        const float* Wi = (mat == 0) ? Wq_i : (mat == 1) ? Wk_i : Wv_i;
        float wr = Wr[d * 128 + c];
        float wi = Wi[d * 128 + c];
        float* Wc = g_Wc[mat];
        Wc[c * 256 + d]               = wr;
        Wc[(c + 128) * 256 + d]       = -wi;
        Wc[c * 256 + 128 + d]         = wi;
        Wc[(c + 128) * 256 + 128 + d] = wr;
    }
    if (idx < 3 * 128) {
        int mat = idx / 128;
        int d   = idx % 128;
        const float* br = (mat == 0) ? bq_r : (mat == 1) ? bk_r : bv_r;
        const float* bi = (mat == 0) ? bq_i : (mat == 1) ? bk_i : bv_i;
        g_bc[mat][d]       = br[d];
        g_bc[mat][128 + d] = bi[d];
    }
}

// ---------------------------------------------------------------------------
// Generic SGEMM (round-3 proven body): 128x128 tile, BK=16, double-buffered.
// MODE 0 (PROJ): A gathered from [re|im] planes, B=g_Wc[sel].
//   sel 0/1 epilogue -> bf16 hi/lo Q/K (same indices as round 3, new dtype).
//   sel 2 epilogue   -> fp32 g_V [m][256] (round-3 exact).
//   sel<0 packs K&V: gridDim.x=4, sel = 1+(bx>>1), n0 = (bx&1)*128.
// MODE 2 (AV): A=g_S [M][1024], B=g_V [K][256], epilogue interleaved complex
//   (round-3 exact, including out-size guard).
// ---------------------------------------------------------------------------
template<int MODE, int N, int K>
__global__ __launch_bounds__(256, 2)
void gemm_kernel(const float* __restrict__ A0, const float* __restrict__ A1,
                 int sel_param, float* __restrict__ Out,
                 const float* __restrict__ gammap, int M, long long out_elems)
{
    const int b   = blockIdx.z;
    const int m0  = blockIdx.y * 128;
    int sel = sel_param;
    int n0  = blockIdx.x * 128;
    if (MODE == 0 && sel_param < 0) {
        sel = 1 + (blockIdx.x >> 1);
        n0  = (blockIdx.x & 1) * 128;
    }
    const int tid = threadIdx.x;
    const int tx  = tid & 15;
    const int ty  = tid >> 4;

    __shared__ float As[2][16][128];
    __shared__ float Bs[2][16][128];

    const float* Ar = nullptr;
    const float* Ai = nullptr;
    const float* Bp = nullptr;
    if (MODE == 0) {
        Ar = A0 + (size_t)b * DIMC * M;
        Ai = A1 + (size_t)b * DIMC * M;
        Bp = g_Wc[sel];
    } else {
        Ar = g_S + (size_t)b * M * K;     // [M][1024]
        Bp = g_V + (size_t)b * K * N;     // [token][256]
    }

    const int a_kl  = tid >> 4;
    const int a_ml8 = (tid & 15) << 3;
    const int a_ml  = tid >> 1;
    const int a_kq  = (tid & 1) << 3;
    const int b_kl  = tid >> 4;
    const int b_nl8 = (tid & 15) << 3;

    float acc[8][8];
#pragma unroll
    for (int i = 0; i < 8; i++)
#pragma unroll
        for (int j = 0; j < 8; j++) acc[i][j] = 0.0f;

    {
        if (MODE == 0) {
            int kg = a_kl;
            const float* src = ((kg < DIMC) ? (Ar + (size_t)kg * M)
                                            : (Ai + (size_t)(kg - DIMC) * M)) + m0 + a_ml8;
            *(float4*)&As[0][a_kl][a_ml8]     = ((const float4*)src)[0];
            *(float4*)&As[0][a_kl][a_ml8 + 4] = ((const float4*)src)[1];
        } else {
            const float* p = Ar + (size_t)(m0 + a_ml) * K + a_kq;
            float4 v0 = ((const float4*)p)[0];
            float4 v1 = ((const float4*)p)[1];
            As[0][a_kq + 0][a_ml] = v0.x; As[0][a_kq + 1][a_ml] = v0.y;
            As[0][a_kq + 2][a_ml] = v0.z; As[0][a_kq + 3][a_ml] = v0.w;
            As[0][a_kq + 4][a_ml] = v1.x; As[0][a_kq + 5][a_ml] = v1.y;
            As[0][a_kq + 6][a_ml] = v1.z; As[0][a_kq + 7][a_ml] = v1.w;
        }
        const float* p = Bp + (size_t)b_kl * N + n0 + b_nl8;
        *(float4*)&Bs[0][b_kl][b_nl8]     = ((const float4*)p)[0];
        *(float4*)&Bs[0][b_kl][b_nl8 + 4] = ((const float4*)p)[1];
    }
    __syncthreads();

    int buf = 0;
#pragma unroll 1
    for (int k0 = 0; k0 < K; k0 += 16) {
        const bool has_next = (k0 + 16 < K);
        float4 ra0, ra1, rb0, rb1;
        if (has_next) {
            const int kn = k0 + 16;
            if (MODE == 0) {
                int kg = kn + a_kl;
                const float* src = ((kg < DIMC) ? (Ar + (size_t)kg * M)
                                                : (Ai + (size_t)(kg - DIMC) * M)) + m0 + a_ml8;
                ra0 = ((const float4*)src)[0];
                ra1 = ((const float4*)src)[1];
            } else {
                const float* p = Ar + (size_t)(m0 + a_ml) * K + kn + a_kq;
                ra0 = ((const float4*)p)[0];
                ra1 = ((const float4*)p)[1];
            }
            const float* p = Bp + (size_t)(kn + b_kl) * N + n0 + b_nl8;
            rb0 = ((const float4*)p)[0];
            rb1 = ((const float4*)p)[1];
        }
#pragma unroll
        for (int kk = 0; kk < 16; kk++) {
            float a[8], bb[8];
            *(float4*)&a[0]  = *(const float4*)&As[buf][kk][ty * 8];
            *(float4*)&a[4]  = *(const float4*)&As[buf][kk][ty * 8 + 4];
            *(float4*)&bb[0] = *(const float4*)&Bs[buf][kk][tx * 8];
            *(float4*)&bb[4] = *(const float4*)&Bs[buf][kk][tx * 8 + 4];
#pragma unroll
            for (int i = 0; i < 8; i++)
#pragma unroll
                for (int j = 0; j < 8; j++)
                    acc[i][j] = fmaf(a[i], bb[j], acc[i][j]);
        }
        if (has_next) {
            int nb = buf ^ 1;
            if (MODE == 0) {
                *(float4*)&As[nb][a_kl][a_ml8]     = ra0;
                *(float4*)&As[nb][a_kl][a_ml8 + 4] = ra1;
            } else {
                As[nb][a_kq + 0][a_ml] = ra0.x; As[nb][a_kq + 1][a_ml] = ra0.y;
                As[nb][a_kq + 2][a_ml] = ra0.z; As[nb][a_kq + 3][a_ml] = ra0.w;
                As[nb][a_kq + 4][a_ml] = ra1.x; As[nb][a_kq + 5][a_ml] = ra1.y;
                As[nb][a_kq + 6][a_ml] = ra1.z; As[nb][a_kq + 7][a_ml] = ra1.w;
            }
            *(float4*)&Bs[nb][b_kl][b_nl8]     = rb0;
            *(float4*)&Bs[nb][b_kl][b_nl8 + 4] = rb1;
        }
        __syncthreads();
        buf ^= 1;
    }

    // ---- epilogue ----
    if (MODE == 0) {
        if (sel == 2) {                         // V -> fp32 (round-3 exact)
            float* C = g_V + (size_t)b * M * 256;
#pragma unroll
            for (int i = 0; i < 8; i++) {
                int m = m0 + ty * 8 + i;
#pragma unroll
                for (int j = 0; j < 8; j++) {
                    int n = n0 + tx * 8 + j;
                    C[(size_t)m * 256 + n] = acc[i][j] + g_bc[sel][n];
                }
            }
        } else {                                // Q/K -> bf16 hi/lo (same indices)
            __nv_bfloat16* Ch = ((sel == 0) ? g_Qh : g_Kh) + (size_t)b * M * 256;
            __nv_bfloat16* Cl = ((sel == 0) ? g_Ql : g_Kl) + (size_t)b * M * 256;
#pragma unroll
            for (int i = 0; i < 8; i++) {
                int m = m0 + ty * 8 + i;
#pragma unroll
                for (int j = 0; j < 8; j++) {
                    int n = n0 + tx * 8 + j;
                    float v = acc[i][j] + g_bc[sel][n];
                    __nv_bfloat16 h, l;
                    split_bf16(v, h, l);
                    Ch[(size_t)m * 256 + n] = h;
                    Cl[(size_t)m * 256 + n] = l;
                }
            }
        }
    } else {                                    // AV epilogue (round-3 exact)
        float g = (gammap != nullptr) ? *gammap : 0.1f;
        bool full = (out_elems >= OUT_FLOATS_FULL);
#pragma unroll
        for (int i = 0; i < 8; i++) {
            int m = m0 + ty * 8 + i;
#pragma unroll
            for (int j = 0; j < 8; j++) {
                int n  = n0 + tx * 8 + j;
                int d  = n & 127;
                int im = n >> 7;
                if (full) {
                    long long idx = (((long long)b * DIMC + d) * M + m) * 2 + im;
                    if (idx < OUT_FLOATS_FULL) Out[idx] = g * acc[i][j];
                } else if (im == 0) {
                    long long idx = ((long long)b * DIMC + d) * M + m;
                    if (idx < out_elems) Out[idx] = g * acc[i][j];
                }
            }
        }
    }
}

// ---------------------------------------------------------------------------
// QK HMMA: S = Q K^T / sqrt(C) on mma.sync bf16 with 3-term hi/lo split.
// 128x128 CTA tile, 8 warps (64x32 each), K-chunk 32.
// Static smem, padded rows (16 data + 4 pad words): fragment-load banks
// (group*20 + tq) mod 32 = all distinct -> conflict-free; no swizzle.
// ---------------------------------------------------------------------------
#define PW 20    // words per smem row
__global__ __launch_bounds__(256)
void qk_hmma()
{
    __shared__ uint32_t sAh[128 * PW];
    __shared__ uint32_t sAl[128 * PW];
    __shared__ uint32_t sBh[128 * PW];
    __shared__ uint32_t sBl[128 * PW];

    const int tid  = threadIdx.x;
    const int wid  = tid >> 5;
    const int lane = tid & 31;
    const int b    = blockIdx.z;
    const int m0   = blockIdx.y * 128;
    const int n0   = blockIdx.x * 128;

    const __nv_bfloat16* Ah = g_Qh + (size_t)b * NTQ * 256;
    const __nv_bfloat16* Al = g_Ql + (size_t)b * NTQ * 256;
    const __nv_bfloat16* Bh = g_Kh + (size_t)b * NSK * 256;
    const __nv_bfloat16* Bl = g_Kl + (size_t)b * NSK * 256;

    const int wm0   = (wid >> 2) * 64;
    const int wn0   = (wid & 3) * 32;
    const int group = lane >> 2;
    const int tq    = lane & 3;

    float acc[4][4][4];
#pragma unroll
    for (int i = 0; i < 4; i++)
#pragma unroll
        for (int j = 0; j < 4; j++)
#pragma unroll
            for (int r = 0; r < 4; r++) acc[i][j][r] = 0.0f;

#pragma unroll 1
    for (int c = 0; c < 8; c++) {            // 8 chunks of 32 k
        const int kc = c * 32;
        // stage: each tile = 128 rows x 4 uint4 groups = 512; 256 threads x 2
#pragma unroll
        for (int it = 0; it < 2; it++) {
            int idx = tid + it * 256;        // 0..511
            int row = idx >> 2;              // 0..127
            int gc  = idx & 3;               // 0..3
            size_t goff = (size_t)(m0 + row) * 256 + kc + gc * 8;
            *(uint4*)&sAh[row * PW + gc * 4] = *(const uint4*)(Ah + goff);
            *(uint4*)&sAl[row * PW + gc * 4] = *(const uint4*)(Al + goff);
            size_t boff = (size_t)(n0 + row) * 256 + kc + gc * 8;
            *(uint4*)&sBh[row * PW + gc * 4] = *(const uint4*)(Bh + boff);
            *(uint4*)&sBl[row * PW + gc * 4] = *(const uint4*)(Bl + boff);
        }
        __syncthreads();

#pragma unroll
        for (int k16 = 0; k16 < 2; k16++) {
            const int w0 = k16 * 8 + tq;
            const int w2 = w0 + 4;
            uint32_t ah[4][4], al[4][4];
#pragma unroll
            for (int i = 0; i < 4; i++) {
                int r0 = (wm0 + i * 16 + group) * PW;
                int r1 = r0 + 8 * PW;
                ah[i][0] = sAh[r0 + w0]; ah[i][1] = sAh[r1 + w0];
                ah[i][2] = sAh[r0 + w2]; ah[i][3] = sAh[r1 + w2];
                al[i][0] = sAl[r0 + w0]; al[i][1] = sAl[r1 + w0];
                al[i][2] = sAl[r0 + w2]; al[i][3] = sAl[r1 + w2];
            }
#pragma unroll
            for (int j = 0; j < 4; j++) {
                int rn = (wn0 + j * 8 + group) * PW;
                uint32_t bh[2], bl[2];
                bh[0] = sBh[rn + w0]; bh[1] = sBh[rn + w2];
                bl[0] = sBl[rn + w0]; bl[1] = sBl[rn + w2];
#pragma unroll
                for (int i = 0; i < 4; i++) {
                    mma16816(acc[i][j], ah[i], bh);
                    mma16816(acc[i][j], al[i], bh);
                    mma16816(acc[i][j], ah[i], bl);
                }
            }
        }
        __syncthreads();
    }

    // epilogue: S * 1/sqrt(128)
    const float alpha = 0.08838834764831845f;
#pragma unroll
    for (int i = 0; i < 4; i++) {
        int m = m0 + wm0 + i * 16 + group;
#pragma unroll
        for (int j = 0; j < 4; j++) {
            int n = n0 + wn0 + j * 8 + tq * 2;
            float2 v0 = make_float2(acc[i][j][0] * alpha, acc[i][j][1] * alpha);
            float2 v1 = make_float2(acc[i][j][2] * alpha, acc[i][j][3] * alpha);
            *(float2*)&g_S[((size_t)b * NTQ + m) * NSK + n]     = v0;
            *(float2*)&g_S[((size_t)b * NTQ + m + 8) * NSK + n] = v1;
        }
    }
}

// ---------------------------------------------------------------------------
// Row softmax over g_S (round-3 exact, in-place fp32).
// ---------------------------------------------------------------------------
__global__ __launch_bounds__(256)
void softmax_kernel()
{
    size_t row = blockIdx.x;
    float* p = g_S + row * (size_t)NSK;
    int t   = threadIdx.x;
    int wid = t >> 5;
    int ln  = t & 31;

    float4 v = ((const float4*)p)[t];
    float mx = fmaxf(fmaxf(v.x, v.y), fmaxf(v.z, v.w));
#pragma unroll
    for (int o = 16; o; o >>= 1) mx = fmaxf(mx, __shfl_xor_sync(0xffffffffu, mx, o));

    __shared__ float red[8];
    if (ln == 0) red[wid] = mx;
    __syncthreads();
    mx = red[0];
#pragma unroll
    for (int w = 1; w < 8; w++) mx = fmaxf(mx, red[w]);

    v.x = __expf(v.x - mx);
    v.y = __expf(v.y - mx);
    v.z = __expf(v.z - mx);
    v.w = __expf(v.w - mx);
    float s = (v.x + v.y) + (v.z + v.w);
#pragma unroll
    for (int o = 16; o; o >>= 1) s += __shfl_xor_sync(0xffffffffu, s, o);

    __syncthreads();
    if (ln == 0) red[wid] = s;
    __syncthreads();
    s = red[0];
#pragma unroll
    for (int w = 1; w < 8; w++) s += red[w];

    float inv = 1.0f / s;
    v.x *= inv; v.y *= inv; v.z *= inv; v.w *= inv;
    ((float4*)p)[t] = v;
}

// ---------------------------------------------------------------------------
// Launch
// ---------------------------------------------------------------------------
extern "C" void kernel_launch(void* const* d_in, const int* in_sizes, int n_in,
                              void* d_out, int out_size)
{
    const float* target_r = (const float*)d_in[0];
    const float* target_i = (const float*)d_in[1];
    const float* source_r = (const float*)d_in[2];
    const float* source_i = (const float*)d_in[3];
    const float* Wq_r = (const float*)d_in[4];
    const float* Wq_i = (const float*)d_in[5];
    const float* bq_r = (const float*)d_in[6];
    const float* bq_i = (const float*)d_in[7];
    const float* Wk_r = (const float*)d_in[8];
    const float* Wk_i = (const float*)d_in[9];
    const float* bk_r = (const float*)d_in[10];
    const float* bk_i = (const float*)d_in[11];
    const float* Wv_r = (const float*)d_in[12];
    const float* Wv_i = (const float*)d_in[13];
    const float* bv_r = (const float*)d_in[14];
    const float* bv_i = (const float*)d_in[15];
    const float* gamma = (n_in >= 17) ? (const float*)d_in[16] : nullptr;
    float* out = (float*)d_out;
    long long out_elems = (long long)out_size;

    // 1) combined weights/biases
    prep_kernel<<<192, 256>>>(Wq_r, Wq_i, Wk_r, Wk_i, Wv_r, Wv_i,
                              bq_r, bq_i, bk_r, bk_i, bv_r, bv_i);

    // 2) projections: Q -> bf16 hi/lo; K (bf16) and V (fp32) packed
    gemm_kernel<0, 256, 256><<<dim3(2, NTQ / 128, BATCH), 256>>>(
        target_r, target_i, 0, nullptr, nullptr, NTQ, 0);
    gemm_kernel<0, 256, 256><<<dim3(4, NSK / 128, BATCH), 256>>>(
        source_r, source_i, -1, nullptr, nullptr, NSK, 0);

    // 3) scores S = Re(Q K^H)/sqrt(C) — HMMA bf16 hi/lo split
    qk_hmma<<<dim3(NSK / 128, NTQ / 128, BATCH), 256>>>();

    // 4) softmax rows (in-place fp32)
    softmax_kernel<<<BATCH * NTQ, 256>>>();

    // 5) out = gamma * (P @ V) — fp32 SIMT (round-3 proven)
    gemm_kernel<2, 256, 1024><<<dim3(2, NTQ / 128, BATCH), 256>>>(
        nullptr, nullptr, 0, out, gamma, NTQ, out_elems);
}

// round 15
// speedup vs baseline: 1.4884x; 1.2056x over previous
#include <cuda_runtime.h>
#include <cuda_bf16.h>
#include <cstdint>

// Problem constants
#define DIMC  128
#define NTQ   4096       // target tokens (64x64)
#define NSK   1024       // source tokens (32x32)
#define BATCH 8
#define OUT_FLOATS_FULL 8388608LL   // 8*128*4096*2 interleaved complex floats

// ---------------------------------------------------------------------------
// Scratch (static __device__ globals; no allocation allowed)
// ---------------------------------------------------------------------------
__device__ float g_Wc[3][256 * 256];                        // combined complex weights
__device__ float g_bc[3][256];                              // combined bias [re|im]
__device__ __align__(16) __nv_bfloat16 g_Qh[(size_t)BATCH * NTQ * 256];   // Q hi/lo [b][m][k]
__device__ __align__(16) __nv_bfloat16 g_Ql[(size_t)BATCH * NTQ * 256];
__device__ __align__(16) __nv_bfloat16 g_Kh[(size_t)BATCH * NSK * 256];   // K hi/lo [b][n][k]
__device__ __align__(16) __nv_bfloat16 g_Kl[(size_t)BATCH * NSK * 256];
__device__ __align__(16) __nv_bfloat16 g_Vth[(size_t)BATCH * 256 * NSK];  // V^T hi/lo [b][d][tok]
__device__ __align__(16) __nv_bfloat16 g_Vtl[(size_t)BATCH * 256 * NSK];
__device__ float g_S[(size_t)BATCH * NTQ * NSK];            // scores (fp32)
__device__ __align__(16) __nv_bfloat16 g_Ph[(size_t)BATCH * NTQ * NSK];   // probs hi/lo
__device__ __align__(16) __nv_bfloat16 g_Pl[(size_t)BATCH * NTQ * NSK];

// ---------------------------------------------------------------------------
// Helpers
// ---------------------------------------------------------------------------
__device__ __forceinline__ void mma16816(float* c, const uint32_t* a, const uint32_t* b) {
    asm volatile("mma.sync.aligned.m16n8k16.row.col.f32.bf16.bf16.f32 "
                 "{%0,%1,%2,%3}, {%4,%5,%6,%7}, {%8,%9}, {%0,%1,%2,%3};"
                 : "+f"(c[0]), "+f"(c[1]), "+f"(c[2]), "+f"(c[3])
                 : "r"(a[0]), "r"(a[1]), "r"(a[2]), "r"(a[3]), "r"(b[0]), "r"(b[1]));
}
__device__ __forceinline__ void split_bf16(float x, __nv_bfloat16& h, __nv_bfloat16& l) {
    h = __float2bfloat16(x);
    l = __float2bfloat16(x - __bfloat162float(h));
}

// ---------------------------------------------------------------------------
// Prep: combined weights + biases (proven).
// ---------------------------------------------------------------------------
__global__ void prep_kernel(const float* __restrict__ Wq_r, const float* __restrict__ Wq_i,
                            const float* __restrict__ Wk_r, const float* __restrict__ Wk_i,
                            const float* __restrict__ Wv_r, const float* __restrict__ Wv_i,
                            const float* __restrict__ bq_r, const float* __restrict__ bq_i,
                            const float* __restrict__ bk_r, const float* __restrict__ bk_i,
                            const float* __restrict__ bv_r, const float* __restrict__ bv_i)
{
    int idx = blockIdx.x * blockDim.x + threadIdx.x;
    if (idx < 3 * 128 * 128) {
        int mat = idx / 16384;
        int r   = idx % 16384;
        int d   = r / 128;
        int c   = r % 128;
        const float* Wr = (mat == 0) ? Wq_r : (mat == 1) ? Wk_r : Wv_r;
        const float* Wi = (mat == 0) ? Wq_i : (mat == 1) ? Wk_i : Wv_i;
        float wr = Wr[d * 128 + c];
        float wi = Wi[d * 128 + c];
        float* Wc = g_Wc[mat];
        Wc[c * 256 + d]               = wr;
        Wc[(c + 128) * 256 + d]       = -wi;
        Wc[c * 256 + 128 + d]         = wi;
        Wc[(c + 128) * 256 + 128 + d] = wr;
    }
    if (idx < 3 * 128) {
        int mat = idx / 128;
        int d   = idx % 128;
        const float* br = (mat == 0) ? bq_r : (mat == 1) ? bk_r : bv_r;
        const float* bi = (mat == 0) ? bq_i : (mat == 1) ? bk_i : bv_i;
        g_bc[mat][d]       = br[d];
        g_bc[mat][128 + d] = bi[d];
    }
}

// ---------------------------------------------------------------------------
// Projection SGEMM (proven body): 128x128 tile, BK=16, double-buffered.
// sel 0/1 -> Q/K bf16 hi/lo K-major; sel 2 -> V^T bf16 hi/lo [d][token].
// sel<0 packs K&V: gridDim.x=4, sel = 1+(bx>>1), n0 = (bx&1)*128.
// ---------------------------------------------------------------------------
__global__ __launch_bounds__(256, 2)
void proj_kernel(const float* __restrict__ A0, const float* __restrict__ A1,
                 int sel_param, int M)
{
    const int b   = blockIdx.z;
    const int m0  = blockIdx.y * 128;
    int sel = sel_param;
    int n0  = blockIdx.x * 128;
    if (sel_param < 0) {
        sel = 1 + (blockIdx.x >> 1);
        n0  = (blockIdx.x & 1) * 128;
    }
    const int tid = threadIdx.x;
    const int tx  = tid & 15;
    const int ty  = tid >> 4;

    __shared__ float As[2][16][128];
    __shared__ float Bs[2][16][128];

    const float* Ar = A0 + (size_t)b * DIMC * M;
    const float* Ai = A1 + (size_t)b * DIMC * M;
    const float* Bp = g_Wc[sel];

    const int a_kl  = tid >> 4;
    const int a_ml8 = (tid & 15) << 3;
    const int b_kl  = tid >> 4;
    const int b_nl8 = (tid & 15) << 3;

    float acc[8][8];
#pragma unroll
    for (int i = 0; i < 8; i++)
#pragma unroll
        for (int j = 0; j < 8; j++) acc[i][j] = 0.0f;

    {
        int kg = a_kl;
        const float* src = ((kg < DIMC) ? (Ar + (size_t)kg * M)
                                        : (Ai + (size_t)(kg - DIMC) * M)) + m0 + a_ml8;
        *(float4*)&As[0][a_kl][a_ml8]     = ((const float4*)src)[0];
        *(float4*)&As[0][a_kl][a_ml8 + 4] = ((const float4*)src)[1];
        const float* p = Bp + (size_t)b_kl * 256 + n0 + b_nl8;
        *(float4*)&Bs[0][b_kl][b_nl8]     = ((const float4*)p)[0];
        *(float4*)&Bs[0][b_kl][b_nl8 + 4] = ((const float4*)p)[1];
    }
    __syncthreads();

    int buf = 0;
#pragma unroll 1
    for (int k0 = 0; k0 < 256; k0 += 16) {
        const bool has_next = (k0 + 16 < 256);
        float4 ra0, ra1, rb0, rb1;
        if (has_next) {
            const int kn = k0 + 16;
            int kg = kn + a_kl;
            const float* src = ((kg < DIMC) ? (Ar + (size_t)kg * M)
                                            : (Ai + (size_t)(kg - DIMC) * M)) + m0 + a_ml8;
            ra0 = ((const float4*)src)[0];
            ra1 = ((const float4*)src)[1];
            const float* p = Bp + (size_t)(kn + b_kl) * 256 + n0 + b_nl8;
            rb0 = ((const float4*)p)[0];
            rb1 = ((const float4*)p)[1];
        }
#pragma unroll
        for (int kk = 0; kk < 16; kk++) {
            float a[8], bb[8];
            *(float4*)&a[0]  = *(const float4*)&As[buf][kk][ty * 8];
            *(float4*)&a[4]  = *(const float4*)&As[buf][kk][ty * 8 + 4];
            *(float4*)&bb[0] = *(const float4*)&Bs[buf][kk][tx * 8];
            *(float4*)&bb[4] = *(const float4*)&Bs[buf][kk][tx * 8 + 4];
#pragma unroll
            for (int i = 0; i < 8; i++)
#pragma unroll
                for (int j = 0; j < 8; j++)
                    acc[i][j] = fmaf(a[i], bb[j], acc[i][j]);
        }
        if (has_next) {
            int nb = buf ^ 1;
            *(float4*)&As[nb][a_kl][a_ml8]     = ra0;
            *(float4*)&As[nb][a_kl][a_ml8 + 4] = ra1;
            *(float4*)&Bs[nb][b_kl][b_nl8]     = rb0;
            *(float4*)&Bs[nb][b_kl][b_nl8 + 4] = rb1;
        }
        __syncthreads();
        buf ^= 1;
    }

    __nv_bfloat16 *Ch, *Cl;
    if (sel == 0)      { Ch = g_Qh + (size_t)b * M * 256;   Cl = g_Ql + (size_t)b * M * 256; }
    else if (sel == 1) { Ch = g_Kh + (size_t)b * M * 256;   Cl = g_Kl + (size_t)b * M * 256; }
    else               { Ch = g_Vth + (size_t)b * 256 * NSK; Cl = g_Vtl + (size_t)b * 256 * NSK; }

#pragma unroll
    for (int i = 0; i < 8; i++) {
        int m = m0 + ty * 8 + i;
#pragma unroll
        for (int j = 0; j < 8; j++) {
            int n = n0 + tx * 8 + j;
            float v = acc[i][j] + g_bc[sel][n];
            __nv_bfloat16 h, l;
            split_bf16(v, h, l);
            if (sel == 2) {                      // V^T: [d][token]
                Ch[(size_t)n * NSK + m] = h;
                Cl[(size_t)n * NSK + m] = l;
            } else {
                Ch[(size_t)m * 256 + n] = h;
                Cl[(size_t)m * 256 + n] = l;
            }
        }
    }
}

// ---------------------------------------------------------------------------
// HMMA GEMM (proven template): D[m][n] = sum_k A[m][k]*B[n][k], bf16 hi/lo
// 3-term split, 128x128 CTA tile, 8 warps (64x32), K-chunk 32, static smem,
// padded rows (16 data + 4 pad words) -> conflict-free plain-LDS fragments.
// MODE 1 (QK): A=Qh/Ql [4096][256], B=Kh/Kl [1024][256], epi g_S * 1/sqrt(128).
// MODE 2 (AV): A=Ph/Pl [4096][1024], B=Vth/Vtl [256][1024], epi interleaved
//              complex out (round-3-proven index formula + guard).
// ---------------------------------------------------------------------------
#define PW 20    // words per smem row
template<int KTOT, int MODE>
__global__ __launch_bounds__(256)
void hmma_gemm(float* __restrict__ Out, const float* __restrict__ gammap,
               long long out_elems)
{
    __shared__ uint32_t sAh[128 * PW];
    __shared__ uint32_t sAl[128 * PW];
    __shared__ uint32_t sBh[128 * PW];
    __shared__ uint32_t sBl[128 * PW];

    const int tid  = threadIdx.x;
    const int wid  = tid >> 5;
    const int lane = tid & 31;
    const int b    = blockIdx.z;
    const int m0   = blockIdx.y * 128;
    const int n0   = blockIdx.x * 128;

    const __nv_bfloat16 *Ah, *Al, *Bh, *Bl;
    if (MODE == 1) {
        Ah = g_Qh + (size_t)b * NTQ * 256;   Al = g_Ql + (size_t)b * NTQ * 256;
        Bh = g_Kh + (size_t)b * NSK * 256;   Bl = g_Kl + (size_t)b * NSK * 256;
    } else {
        Ah = g_Ph + (size_t)b * NTQ * NSK;   Al = g_Pl + (size_t)b * NTQ * NSK;
        Bh = g_Vth + (size_t)b * 256 * NSK;  Bl = g_Vtl + (size_t)b * 256 * NSK;
    }

    const int wm0   = (wid >> 2) * 64;
    const int wn0   = (wid & 3) * 32;
    const int group = lane >> 2;
    const int tq    = lane & 3;

    float acc[4][4][4];
#pragma unroll
    for (int i = 0; i < 4; i++)
#pragma unroll
        for (int j = 0; j < 4; j++)
#pragma unroll
            for (int r = 0; r < 4; r++) acc[i][j][r] = 0.0f;

#pragma unroll 1
    for (int c = 0; c < KTOT / 32; c++) {
        const int kc = c * 32;
#pragma unroll
        for (int it = 0; it < 2; it++) {
            int idx = tid + it * 256;        // 0..511
            int row = idx >> 2;              // 0..127
            int gc  = idx & 3;               // 0..3
            size_t goff = (size_t)(m0 + row) * KTOT + kc + gc * 8;
            *(uint4*)&sAh[row * PW + gc * 4] = *(const uint4*)(Ah + goff);
            *(uint4*)&sAl[row * PW + gc * 4] = *(const uint4*)(Al + goff);
            size_t boff = (size_t)(n0 + row) * KTOT + kc + gc * 8;
            *(uint4*)&sBh[row * PW + gc * 4] = *(const uint4*)(Bh + boff);
            *(uint4*)&sBl[row * PW + gc * 4] = *(const uint4*)(Bl + boff);
        }
        __syncthreads();

#pragma unroll
        for (int k16 = 0; k16 < 2; k16++) {
            const int w0 = k16 * 8 + tq;
            const int w2 = w0 + 4;
            uint32_t ah[4][4], al[4][4];
#pragma unroll
            for (int i = 0; i < 4; i++) {
                int r0 = (wm0 + i * 16 + group) * PW;
                int r1 = r0 + 8 * PW;
                ah[i][0] = sAh[r0 + w0]; ah[i][1] = sAh[r1 + w0];
                ah[i][2] = sAh[r0 + w2]; ah[i][3] = sAh[r1 + w2];
                al[i][0] = sAl[r0 + w0]; al[i][1] = sAl[r1 + w0];
                al[i][2] = sAl[r0 + w2]; al[i][3] = sAl[r1 + w2];
            }
#pragma unroll
            for (int j = 0; j < 4; j++) {
                int rn = (wn0 + j * 8 + group) * PW;
                uint32_t bh[2], bl[2];
                bh[0] = sBh[rn + w0]; bh[1] = sBh[rn + w2];
                bl[0] = sBl[rn + w0]; bl[1] = sBl[rn + w2];
#pragma unroll
                for (int i = 0; i < 4; i++) {
                    mma16816(acc[i][j], ah[i], bh);
                    mma16816(acc[i][j], al[i], bh);
                    mma16816(acc[i][j], ah[i], bl);
                }
            }
        }
        __syncthreads();
    }

    // ---- epilogue ----
    if (MODE == 1) {
        const float alpha = 0.08838834764831845f;   // 1/sqrt(128)
#pragma unroll
        for (int i = 0; i < 4; i++) {
            int m = m0 + wm0 + i * 16 + group;
#pragma unroll
            for (int j = 0; j < 4; j++) {
                int n = n0 + wn0 + j * 8 + tq * 2;
                float2 v0 = make_float2(acc[i][j][0] * alpha, acc[i][j][1] * alpha);
                float2 v1 = make_float2(acc[i][j][2] * alpha, acc[i][j][3] * alpha);
                *(float2*)&g_S[((size_t)b * NTQ + m) * NSK + n]     = v0;
                *(float2*)&g_S[((size_t)b * NTQ + m + 8) * NSK + n] = v1;
            }
        }
    } else {
        float g = (gammap != nullptr) ? *gammap : 0.1f;
        bool full = (out_elems >= OUT_FLOATS_FULL);
        const int im = n0 >> 7;     // n0 in {0,128}: 0=real, 1=imag half
#pragma unroll
        for (int i = 0; i < 4; i++) {
            int m = m0 + wm0 + i * 16 + group;
#pragma unroll
            for (int j = 0; j < 4; j++) {
                int d = wn0 + j * 8 + tq * 2;       // channel 0..127
#pragma unroll
                for (int r = 0; r < 4; r++) {
                    int dd = d + (r & 1);
                    int mm = m + ((r >> 1) << 3);
                    long long idx = (((long long)b * DIMC + dd) * NTQ + mm) * 2 + im;
                    if (full) {
                        if (idx < OUT_FLOATS_FULL) Out[idx] = g * acc[i][j][r];
                    } else if (im == 0) {
                        long long ridx = ((long long)b * DIMC + dd) * NTQ + mm;
                        if (ridx < out_elems) Out[ridx] = g * acc[i][j][r];
                    }
                }
            }
        }
    }
}

// ---------------------------------------------------------------------------
// Row softmax over g_S: 32768 rows x 1024; emits P as bf16 hi/lo.
// ---------------------------------------------------------------------------
__global__ __launch_bounds__(256)
void softmax_kernel()
{
    size_t row = blockIdx.x;
    const float* p = g_S + row * (size_t)NSK;
    int t   = threadIdx.x;
    int wid = t >> 5;
    int ln  = t & 31;

    float4 v = ((const float4*)p)[t];
    float mx = fmaxf(fmaxf(v.x, v.y), fmaxf(v.z, v.w));
#pragma unroll
    for (int o = 16; o; o >>= 1) mx = fmaxf(mx, __shfl_xor_sync(0xffffffffu, mx, o));

    __shared__ float red[8];
    if (ln == 0) red[wid] = mx;
    __syncthreads();
    mx = red[0];
#pragma unroll
    for (int w = 1; w < 8; w++) mx = fmaxf(mx, red[w]);

    v.x = __expf(v.x - mx);
    v.y = __expf(v.y - mx);
    v.z = __expf(v.z - mx);
    v.w = __expf(v.w - mx);
    float s = (v.x + v.y) + (v.z + v.w);
#pragma unroll
    for (int o = 16; o; o >>= 1) s += __shfl_xor_sync(0xffffffffu, s, o);

    __syncthreads();
    if (ln == 0) red[wid] = s;
    __syncthreads();
    s = red[0];
#pragma unroll
    for (int w = 1; w < 8; w++) s += red[w];

    float inv = 1.0f / s;
    v.x *= inv; v.y *= inv; v.z *= inv; v.w *= inv;

    __nv_bfloat16 h[4], l[4];
    split_bf16(v.x, h[0], l[0]);
    split_bf16(v.y, h[1], l[1]);
    split_bf16(v.z, h[2], l[2]);
    split_bf16(v.w, h[3], l[3]);
    size_t off = row * (size_t)NSK + t * 4;
    *(uint2*)(g_Ph + off) = *(uint2*)h;
    *(uint2*)(g_Pl + off) = *(uint2*)l;
}

// ---------------------------------------------------------------------------
// Launch
// ---------------------------------------------------------------------------
extern "C" void kernel_launch(void* const* d_in, const int* in_sizes, int n_in,
                              void* d_out, int out_size)
{
    const float* target_r = (const float*)d_in[0];
    const float* target_i = (const float*)d_in[1];
    const float* source_r = (const float*)d_in[2];
    const float* source_i = (const float*)d_in[3];
    const float* Wq_r = (const float*)d_in[4];
    const float* Wq_i = (const float*)d_in[5];
    const float* bq_r = (const float*)d_in[6];
    const float* bq_i = (const float*)d_in[7];
    const float* Wk_r = (const float*)d_in[8];
    const float* Wk_i = (const float*)d_in[9];
    const float* bk_r = (const float*)d_in[10];
    const float* bk_i = (const float*)d_in[11];
    const float* Wv_r = (const float*)d_in[12];
    const float* Wv_i = (const float*)d_in[13];
    const float* bv_r = (const float*)d_in[14];
    const float* bv_i = (const float*)d_in[15];
    const float* gamma = (n_in >= 17) ? (const float*)d_in[16] : nullptr;
    float* out = (float*)d_out;
    long long out_elems = (long long)out_size;

    // 1) combined weights/biases
    prep_kernel<<<192, 256>>>(Wq_r, Wq_i, Wk_r, Wk_i, Wv_r, Wv_i,
                              bq_r, bq_i, bk_r, bk_i, bv_r, bv_i);

    // 2) projections: Q -> bf16 hi/lo; K (bf16) and V^T (bf16) packed
    proj_kernel<<<dim3(2, NTQ / 128, BATCH), 256>>>(target_r, target_i, 0, NTQ);
    proj_kernel<<<dim3(4, NSK / 128, BATCH), 256>>>(source_r, source_i, -1, NSK);

    // 3) scores S = Re(Q K^H)/sqrt(C) — HMMA
    hmma_gemm<256, 1><<<dim3(NSK / 128, NTQ / 128, BATCH), 256>>>(nullptr, nullptr, 0);

    // 4) softmax -> P bf16 hi/lo
    softmax_kernel<<<BATCH * NTQ, 256>>>();

    // 5) out = gamma * (P V) — HMMA, interleaved complex epilogue
    hmma_gemm<1024, 2><<<dim3(2, NTQ / 128, BATCH), 256>>>(out, gamma, out_elems);
}